// round 3
// baseline (speedup 1.0000x reference)
#include <cuda_runtime.h>
#include <math.h>

#define Bn 32
#define Ln 8192
#define Cn 64
#define Mn 64           // retained modes
#define Jn 128          // 2*Mn (cos/sin rows)
#define JG 192          // Jn + Cn (spectral + pointwise contraction)
#define NCHUNK 16
#define LCHUNK 512      // Ln / NCHUNK

typedef unsigned long long ull;

// ---- scratch (device globals; no allocation allowed) ----
__device__ float g_basisT[Ln * Jn];                // [l][j]: j=2k -> cos, 2k+1 -> sin of 2*pi*k*l/L
__device__ float g_Aw[Mn * Cn * Cn];               // [k][i][o] = alpha_k * Wr[i][o][k]
__device__ float g_Bw[Mn * Cn * Cn];               // [k][i][o] = alpha_k * Wi[i][o][k]
__device__ float g_Ppart[NCHUNK * Bn * Jn * Cn];   // DFT partials [ch][b][j][c]
__device__ float g_P[Bn * Jn * Cn];                // reduced DFT  [b][j][c]
__device__ float g_G[Bn * JG * Cn];                // stage-3 B operand [b][j][o]

// ---- packed f32x2 helpers ----
__device__ __forceinline__ ull fma2(ull a, ull b, ull c) {
    ull d;
    asm("fma.rn.f32x2 %0, %1, %2, %3;" : "=l"(d) : "l"(a), "l"(b), "l"(c));
    return d;
}
__device__ __forceinline__ float2 unpack2(ull v) {
    float2 r;
    asm("mov.b64 {%0, %1}, %2;" : "=f"(r.x), "=f"(r.y) : "l"(v));
    return r;
}

// ---------------------------------------------------------------------------
// Basis table (transposed): exact integer phase reduction -> theta in [0, 2*pi)
// g_basisT[l*128 + 2k] = cos, [l*128 + 2k+1] = sin.  Coalesced float2 writes.
// ---------------------------------------------------------------------------
__global__ void k_basis() {
    int g = blockIdx.x * blockDim.x + threadIdx.x;   // 0 .. Mn*Ln-1
    int k = g & 63;
    int l = g >> 6;
    int m = (k * l) & (Ln - 1); // exact: k*l < 2^19
    float th = (float)m * (6.2831853071795864769f / (float)Ln);
    float s, c;
    sincosf(th, &s, &c);
    ((float2*)g_basisT)[l * 64 + k] = make_float2(c, s);
}

// ---------------------------------------------------------------------------
// Transpose spectral weights to [k][i][o] with irfft scale folded in
// ---------------------------------------------------------------------------
__global__ void k_prepW(const float* __restrict__ wr, const float* __restrict__ wi) {
    int g = blockIdx.x * blockDim.x + threadIdx.x;   // [k][i][o] flat
    int o = g & 63;
    int i = (g >> 6) & 63;
    int k = g >> 12;
    float alpha = (k == 0 ? 1.0f : 2.0f) / (float)Ln;
    int widx = (i * Cn + o) * Mn + k;                // source layout [i][o][k]
    g_Aw[g] = alpha * wr[widx];
    g_Bw[g] = alpha * wi[widx];
}

// ---------------------------------------------------------------------------
// Stage 1: truncated forward DFT as GEMM.  P[b][j][c] = sum_l basisT[l][j]*x[b][l][c]
// FFMA2: accumulators paired along j (M dim); B (x) duplicated into both lanes.
// Grid: (NCHUNK, Bn), 256 threads.  Tile: 128(j) x 64(c), K=512 per block.
// ---------------------------------------------------------------------------
__global__ void __launch_bounds__(256) k_dft(const float* __restrict__ x) {
    int ch = blockIdx.x, b = blockIdx.y;
    int l0 = ch * LCHUNK;
    __shared__ __align__(16) float  Es2[16 * 128];   // [ll][j]  (A, natural j-pairs)
    __shared__ __align__(16) float2 Xs2[16 * 64];    // [ll][c]  (B, dup lanes)
    int t  = threadIdx.x;
    int tx = t & 15, ty = t >> 4;
    int j0 = ty * 8, c0 = tx * 4;

    ull acc[4][4];                                   // [jpair][c]
#pragma unroll
    for (int p = 0; p < 4; p++)
#pragma unroll
        for (int cc = 0; cc < 4; cc++) acc[p][cc] = 0ULL;

    for (int ks = 0; ks < LCHUNK; ks += 16) {
#pragma unroll
        for (int i = 0; i < 8; i++) {                // 16x128 basisT tile, coalesced on j
            int idx = t + i * 256;
            int j = idx & 127, ll = idx >> 7;
            Es2[ll * 128 + j] = g_basisT[(l0 + ks + ll) * Jn + j];
        }
#pragma unroll
        for (int i = 0; i < 4; i++) {                // 16x64 x tile, dup into both lanes
            int idx = t + i * 256;
            int c = idx & 63, ll = idx >> 6;
            float v = x[(b * Ln + l0 + ks + ll) * Cn + c];
            Xs2[ll * 64 + c] = make_float2(v, v);
        }
        __syncthreads();
#pragma unroll
        for (int ll = 0; ll < 16; ll++) {
            ull a[4];
#pragma unroll
            for (int p = 0; p < 4; p++)
                a[p] = *(const ull*)&Es2[ll * 128 + j0 + 2 * p];
            ulonglong2 b01 = *(const ulonglong2*)&Xs2[ll * 64 + c0];
            ulonglong2 b23 = *(const ulonglong2*)&Xs2[ll * 64 + c0 + 2];
#pragma unroll
            for (int p = 0; p < 4; p++) {
                acc[p][0] = fma2(a[p], b01.x, acc[p][0]);
                acc[p][1] = fma2(a[p], b01.y, acc[p][1]);
                acc[p][2] = fma2(a[p], b23.x, acc[p][2]);
                acc[p][3] = fma2(a[p], b23.y, acc[p][3]);
            }
        }
        __syncthreads();
    }
    float* dst = &g_Ppart[((ch * Bn + b) * Jn) * Cn];
#pragma unroll
    for (int p = 0; p < 4; p++) {
        float2 v0 = unpack2(acc[p][0]), v1 = unpack2(acc[p][1]);
        float2 v2 = unpack2(acc[p][2]), v3 = unpack2(acc[p][3]);
        *(float4*)&dst[(j0 + 2 * p)     * Cn + c0] = make_float4(v0.x, v1.x, v2.x, v3.x);
        *(float4*)&dst[(j0 + 2 * p + 1) * Cn + c0] = make_float4(v0.y, v1.y, v2.y, v3.y);
    }
}

// Deterministic partial reduction
__global__ void k_reduceP() {
    int g = blockIdx.x * blockDim.x + threadIdx.x;   // Bn*Jn*Cn
    float s = 0.0f;
#pragma unroll
    for (int ch = 0; ch < NCHUNK; ch++)
        s += g_Ppart[ch * (Bn * Jn * Cn) + g];
    g_P[g] = s;
}

// ---------------------------------------------------------------------------
// Stage 2: per-mode complex mix.  P0=XFr, P1=-XFi (sign of sin row).
//   G[2k]   =  alpha*TFr = sum_i P0*A + P1*B
//   G[2k+1] = -alpha*TFi = sum_i P1*A - P0*B
// ---------------------------------------------------------------------------
__global__ void k_mix() {
    int k = blockIdx.x, b = blockIdx.y, o = threadIdx.x;
    __shared__ float P0[Cn], P1[Cn];
    P0[o] = g_P[(b * Jn + 2 * k) * Cn + o];
    P1[o] = g_P[(b * Jn + 2 * k + 1) * Cn + o];
    __syncthreads();
    float gr = 0.0f, gi = 0.0f;
#pragma unroll 8
    for (int i = 0; i < Cn; i++) {
        float a  = g_Aw[(k * Cn + i) * Cn + o];
        float bb = g_Bw[(k * Cn + i) * Cn + o];
        float pr = P0[i], pi = P1[i];
        gr += pr * a + pi * bb;
        gi += pi * a - pr * bb;
    }
    g_G[(b * JG + 2 * k) * Cn + o]     = gr;
    g_G[(b * JG + 2 * k + 1) * Cn + o] = gi;
}

// Fill rows 128..191 of G with pw_weight^T (per batch, for uniform stage-3 GEMM)
__global__ void k_pwfill(const float* __restrict__ pw) {
    int b = blockIdx.x, t = threadIdx.x;
#pragma unroll
    for (int i = 0; i < 16; i++) {
        int idx = t + i * 256;
        int o = idx & 63, ic = idx >> 6;
        g_G[(b * JG + Jn + ic) * Cn + o] = pw[o * Cn + ic];
    }
}

// ---------------------------------------------------------------------------
// Stage 3: fused inverse-DFT + pointwise GEMM + bias.
//   out[b][l][o] = sum_{j<192} BigA[l][j] * G[b][j][o] + bias[o]
//   BigA[l][0:128] = basisT rows, BigA[l][128:192] = x[b][l][:]
// FFMA2: accumulators paired along l (M dim); G duplicated into both lanes.
// Grid: (64 l-tiles, Bn), 256 threads, tile 128(l) x 64(o), K=192.
// ---------------------------------------------------------------------------
__global__ void __launch_bounds__(256) k_out(const float* __restrict__ x,
                                             const float* __restrict__ bias,
                                             float* __restrict__ out) {
    int lt = blockIdx.x, b = blockIdx.y;
    int l0 = lt * 128;
    extern __shared__ __align__(16) float sm[];
    float2* Gs2 = (float2*)sm;                 // 192*64 float2 (dup lanes) = 96 KB
    float*  As2 = sm + 2 * JG * Cn;            // [jj][r], stride 130 (bank-spread)
    int t  = threadIdx.x;
    int tx = t & 15, ty = t >> 4;
    int r0 = ty * 8, c0 = tx * 4;

#pragma unroll
    for (int i = 0; i < 48; i++) {             // preload full G[b], dup both lanes
        int idx = t + i * 256;
        float v = g_G[b * (JG * Cn) + idx];
        Gs2[idx] = make_float2(v, v);
    }

    ull acc[4][4];                             // [lpair][c]
#pragma unroll
    for (int p = 0; p < 4; p++)
#pragma unroll
        for (int cc = 0; cc < 4; cc++) acc[p][cc] = 0ULL;

    for (int jc = 0; jc < JG; jc += 16) {
        __syncthreads();                       // protect As2 reuse (covers Gs2 on iter 0)
        if (jc < Jn) {
#pragma unroll
            for (int i = 0; i < 8; i++) {      // basisT tile -> As2[jj][r]
                int idx = t + i * 256;
                int jj = idx & 15, r = idx >> 4;
                As2[jj * 130 + r] = g_basisT[(l0 + r) * Jn + jc + jj];
            }
        } else {
#pragma unroll
            for (int i = 0; i < 8; i++) {      // x tile -> As2[jj][r]
                int idx = t + i * 256;
                int jj = idx & 15, r = idx >> 4;
                As2[jj * 130 + r] = x[(b * Ln + l0 + r) * Cn + (jc - Jn) + jj];
            }
        }
        __syncthreads();
#pragma unroll
        for (int jj = 0; jj < 16; jj++) {
            ull a[4];
#pragma unroll
            for (int p = 0; p < 4; p++)
                a[p] = *(const ull*)&As2[jj * 130 + r0 + 2 * p];
            ulonglong2 b01 = *(const ulonglong2*)&Gs2[(jc + jj) * 64 + c0];
            ulonglong2 b23 = *(const ulonglong2*)&Gs2[(jc + jj) * 64 + c0 + 2];
#pragma unroll
            for (int p = 0; p < 4; p++) {
                acc[p][0] = fma2(a[p], b01.x, acc[p][0]);
                acc[p][1] = fma2(a[p], b01.y, acc[p][1]);
                acc[p][2] = fma2(a[p], b23.x, acc[p][2]);
                acc[p][3] = fma2(a[p], b23.y, acc[p][3]);
            }
        }
    }

    float b0 = bias[c0], b1 = bias[c0 + 1], b2 = bias[c0 + 2], b3 = bias[c0 + 3];
#pragma unroll
    for (int p = 0; p < 4; p++) {
        float2 v0 = unpack2(acc[p][0]), v1 = unpack2(acc[p][1]);
        float2 v2 = unpack2(acc[p][2]), v3 = unpack2(acc[p][3]);
        int row0 = l0 + r0 + 2 * p;
        *(float4*)&out[(b * Ln + row0)     * Cn + c0] =
            make_float4(v0.x + b0, v1.x + b1, v2.x + b2, v3.x + b3);
        *(float4*)&out[(b * Ln + row0 + 1) * Cn + c0] =
            make_float4(v0.y + b0, v1.y + b1, v2.y + b2, v3.y + b3);
    }
}

// ---------------------------------------------------------------------------
extern "C" void kernel_launch(void* const* d_in, const int* in_sizes, int n_in,
                              void* d_out, int out_size) {
    const float* x    = (const float*)d_in[0];
    const float* wr   = (const float*)d_in[1];
    const float* wi   = (const float*)d_in[2];
    const float* pw   = (const float*)d_in[3];
    const float* bias = (const float*)d_in[4];
    float* out = (float*)d_out;

    k_basis<<<(Mn * Ln) / 256, 256>>>();
    k_prepW<<<(Mn * Cn * Cn) / 256, 256>>>(wr, wi);
    k_dft<<<dim3(NCHUNK, Bn), 256>>>(x);
    k_reduceP<<<(Bn * Jn * Cn) / 256, 256>>>();
    k_mix<<<dim3(Mn, Bn), Cn>>>();
    k_pwfill<<<Bn, 256>>>(pw);

    int smem = (2 * JG * Cn + 16 * 130) * (int)sizeof(float);   // 106624 B
    cudaFuncSetAttribute(k_out, cudaFuncAttributeMaxDynamicSharedMemorySize, smem);
    k_out<<<dim3(Ln / 128, Bn), 256, smem>>>(x, bias, out);
}

// round 5
// speedup vs baseline: 2.8568x; 2.8568x over previous
#include <cuda_runtime.h>
#include <math.h>
#include <stdint.h>

#define Bn 32
#define Ln 8192
#define Cn 64
#define Mn 64
#define Jn 128          // 2*Mn (cos/sin rows)
#define JG 192          // Jn + Cn
#define NCH 8           // stage-1 K chunks (K=1024 each)

// ---- scratch (device globals; no allocation allowed) ----
__device__ float g_b1frag[8 * 1024 * 32 * 4];   // stage-1 A frags [mt][ks][lane][q]  (4MB)
__device__ float g_b3frag[64 * 8 * 16 * 32 * 4];// stage-3 A frags [lt][mt][ks][lane][q] (4MB)
__device__ float g_Aw[Mn * Cn * Cn];            // [k][i][o] = alpha_k * Wr
__device__ float g_Bw[Mn * Cn * Cn];            // [k][i][o] = alpha_k * Wi
__device__ float g_Pp[NCH * Bn * Jn * Cn];      // stage-1 partials [ch][b][j][c] (8MB)
__device__ float g_P[Bn * Jn * Cn];
__device__ float g_G[Bn * JG * Cn];             // stage-3 B operand [b][j][o] (fp32)

// ---------------- helpers ----------------
__device__ __forceinline__ float totf32(float x) {
    uint32_t u;
    asm("cvt.rn.tf32.f32 %0, %1;" : "=r"(u) : "f"(x));
    return __uint_as_float(u);
}
__device__ __forceinline__ uint32_t fau(float x) { return __float_as_uint(x); }

// m16n8k8 tf32 mma: D(16x8 f32) += A(16x8 tf32, row) * B(8x8 tf32, col)
__device__ __forceinline__ void mma_t32(float c[4], const uint32_t a[4],
                                        uint32_t b0, uint32_t b1) {
    asm volatile(
        "mma.sync.aligned.m16n8k8.row.col.f32.tf32.tf32.f32 "
        "{%0,%1,%2,%3}, {%4,%5,%6,%7}, {%8,%9}, {%0,%1,%2,%3};"
        : "+f"(c[0]), "+f"(c[1]), "+f"(c[2]), "+f"(c[3])
        : "r"(a[0]), "r"(a[1]), "r"(a[2]), "r"(a[3]), "r"(b0), "r"(b1));
}

// ---------------------------------------------------------------------------
// Stage-1 A fragments: A[j][l], j = mt*16 + row, l = ks*8 + col.
// Fragment q: row += (q&1)*8, col += (q>>1)*4.  j even -> cos, odd -> sin.
// ---------------------------------------------------------------------------
__global__ void k_basis1() {
    int g = blockIdx.x * blockDim.x + threadIdx.x;   // 1M
    int q = g & 3, lane = (g >> 2) & 31, ks = (g >> 7) & 1023, mt = g >> 17;
    int j = mt * 16 + (lane >> 2) + (q & 1) * 8;
    int l = ks * 8 + (lane & 3) + ((q >> 1) & 1) * 4;
    int km = j >> 1;
    int m = (km * l) & (Ln - 1);                     // exact: < 2^19
    float th = (float)m * (6.2831853071795864769f / (float)Ln);
    float s, c; sincosf(th, &s, &c);
    g_b1frag[g] = totf32((j & 1) ? s : c);
}

// Stage-3 A fragments: A[l][j], l = lt*128 + mt*16 + row, j = ks*8 + col.
__global__ void k_basis3() {
    int g = blockIdx.x * blockDim.x + threadIdx.x;   // 1M
    int q = g & 3, lane = (g >> 2) & 31, ks = (g >> 7) & 15;
    int mt = (g >> 11) & 7, lt = g >> 14;
    int l = lt * 128 + mt * 16 + (lane >> 2) + (q & 1) * 8;
    int j = ks * 8 + (lane & 3) + ((q >> 1) & 1) * 4;
    int km = j >> 1;
    int m = (km * l) & (Ln - 1);
    float th = (float)m * (6.2831853071795864769f / (float)Ln);
    float s, c; sincosf(th, &s, &c);
    g_b3frag[g] = totf32((j & 1) ? s : c);
}

__global__ void k_prepW(const float* __restrict__ wr, const float* __restrict__ wi) {
    int g = blockIdx.x * blockDim.x + threadIdx.x;
    int o = g & 63, i = (g >> 6) & 63, k = g >> 12;
    float alpha = (k == 0 ? 1.0f : 2.0f) / (float)Ln;
    int widx = (i * Cn + o) * Mn + k;
    g_Aw[g] = alpha * wr[widx];
    g_Bw[g] = alpha * wi[widx];
}

// ---------------------------------------------------------------------------
// Stage 1: P[j=128][c=64] = sum_l basis[j,l]*x[l,c]; K=1024 per block.
// 8 warps; warp w owns j-strip [w*16, w*16+16), all 8 n-tiles.
// ---------------------------------------------------------------------------
__global__ void __launch_bounds__(256) k_dft(const float* __restrict__ x) {
    int ch = blockIdx.x, b = blockIdx.y;
    __shared__ float Xs[32 * 72];                    // [l-row][c], stride 72 (conflict-free)
    int t = threadIdx.x, w = t >> 5, lane = t & 31;
    int g = lane >> 2, tg = lane & 3;

    float c[8][4];
#pragma unroll
    for (int nt = 0; nt < 8; nt++)
#pragma unroll
        for (int q = 0; q < 4; q++) c[nt][q] = 0.0f;

    const float4* ap = (const float4*)g_b1frag + ((size_t)(w * 1024 + ch * 128) * 32 + lane);
    const float* xb = x + (size_t)b * Ln * Cn + (size_t)ch * 1024 * Cn;

    for (int kc = 0; kc < 32; kc++) {
#pragma unroll
        for (int i = 0; i < 8; i++) {                // stage 32 x-rows (2048 elems)
            int idx = t + i * 256;
            int row = idx >> 6, col = idx & 63;
            Xs[row * 72 + col] = totf32(xb[(kc * 32 + row) * Cn + col]);
        }
        __syncthreads();
#pragma unroll
        for (int ks4 = 0; ks4 < 4; ks4++) {
            float4 af = ap[(kc * 4 + ks4) * 32];
            uint32_t a[4] = { fau(af.x), fau(af.y), fau(af.z), fau(af.w) };
            int kr0 = ks4 * 8 + tg;
#pragma unroll
            for (int nt = 0; nt < 8; nt++) {
                uint32_t b0 = fau(Xs[kr0 * 72 + nt * 8 + g]);
                uint32_t b1 = fau(Xs[(kr0 + 4) * 72 + nt * 8 + g]);
                mma_t32(c[nt], a, b0, b1);
            }
        }
        __syncthreads();
    }

    float* dst = g_Pp + ((size_t)(ch * Bn + b) * Jn) * Cn;
    int j0 = w * 16 + g;
#pragma unroll
    for (int nt = 0; nt < 8; nt++) {
        *(float2*)&dst[j0 * Cn + nt * 8 + 2 * tg]       = make_float2(c[nt][0], c[nt][1]);
        *(float2*)&dst[(j0 + 8) * Cn + nt * 8 + 2 * tg] = make_float2(c[nt][2], c[nt][3]);
    }
}

__global__ void k_reduceP() {
    int g = blockIdx.x * blockDim.x + threadIdx.x;
    float s = 0.0f;
#pragma unroll
    for (int ch = 0; ch < NCH; ch++)
        s += g_Pp[(size_t)ch * (Bn * Jn * Cn) + g];
    g_P[g] = s;
}

// ---------------------------------------------------------------------------
// Stage 2: complex mix (validated in R2).  P0=XFr, P1=-XFi.
// ---------------------------------------------------------------------------
__global__ void k_mix() {
    int k = blockIdx.x, b = blockIdx.y, o = threadIdx.x;
    __shared__ float P0[Cn], P1[Cn];
    P0[o] = g_P[(b * Jn + 2 * k) * Cn + o];
    P1[o] = g_P[(b * Jn + 2 * k + 1) * Cn + o];
    __syncthreads();
    float gr = 0.0f, gi = 0.0f;
#pragma unroll 8
    for (int i = 0; i < Cn; i++) {
        float a  = g_Aw[(k * Cn + i) * Cn + o];
        float bb = g_Bw[(k * Cn + i) * Cn + o];
        float pr = P0[i], pi = P1[i];
        gr += pr * a + pi * bb;
        gi += pi * a - pr * bb;
    }
    g_G[(b * JG + 2 * k) * Cn + o]     = gr;
    g_G[(b * JG + 2 * k + 1) * Cn + o] = gi;
}

__global__ void k_pwfill(const float* __restrict__ pw) {
    int b = blockIdx.x, t = threadIdx.x;
#pragma unroll
    for (int i = 0; i < 16; i++) {
        int idx = t + i * 256;
        int o = idx & 63, ic = idx >> 6;
        g_G[(b * JG + Jn + ic) * Cn + o] = pw[o * Cn + ic];
    }
}

// ---------------------------------------------------------------------------
// Stage 3: out[l=128][o=64] = sum_{j<192} bigA[l,j]*G[j,o] + bias.
// ksteps 0..15: basis frags from global; 16..23: x rows from smem As.
// ---------------------------------------------------------------------------
__global__ void __launch_bounds__(256) k_out(const float* __restrict__ x,
                                             const float* __restrict__ bias,
                                             float* __restrict__ out) {
    int lt = blockIdx.x, b = blockIdx.y;
    extern __shared__ __align__(16) float sm[];
    float* Gs = sm;                                  // [192][72]
    float* As = sm + 192 * 72;                       // [128][72]
    int t = threadIdx.x, w = t >> 5, lane = t & 31;
    int g = lane >> 2, tg = lane & 3;

#pragma unroll
    for (int i = 0; i < 48; i++) {                   // stage G (12288 elems) as tf32
        int idx = t + i * 256;
        int j = idx >> 6, o = idx & 63;
        Gs[j * 72 + o] = totf32(g_G[((size_t)b * JG + j) * Cn + o]);
    }
#pragma unroll
    for (int i = 0; i < 32; i++) {                   // stage x rows (8192 elems)
        int idx = t + i * 256;
        int r = idx >> 6, cc = idx & 63;
        As[r * 72 + cc] = totf32(x[((size_t)b * Ln + lt * 128 + r) * Cn + cc]);
    }
    __syncthreads();

    float c[8][4];
#pragma unroll
    for (int nt = 0; nt < 8; nt++)
#pragma unroll
        for (int q = 0; q < 4; q++) c[nt][q] = 0.0f;

    const float4* ap = (const float4*)g_b3frag + ((size_t)((lt * 8 + w) * 16) * 32 + lane);
#pragma unroll
    for (int ks = 0; ks < 16; ks++) {                // basis part (K 0..127)
        float4 af = ap[ks * 32];
        uint32_t a[4] = { fau(af.x), fau(af.y), fau(af.z), fau(af.w) };
        int kr0 = ks * 8 + tg;
#pragma unroll
        for (int nt = 0; nt < 8; nt++) {
            uint32_t b0 = fau(Gs[kr0 * 72 + nt * 8 + g]);
            uint32_t b1 = fau(Gs[(kr0 + 4) * 72 + nt * 8 + g]);
            mma_t32(c[nt], a, b0, b1);
        }
    }
#pragma unroll
    for (int ks = 0; ks < 8; ks++) {                 // x part (K 128..191)
        int kk = ks * 8 + tg;
        int r0 = w * 16 + g;
        uint32_t a[4];
        a[0] = fau(As[r0 * 72 + kk]);
        a[1] = fau(As[(r0 + 8) * 72 + kk]);
        a[2] = fau(As[r0 * 72 + kk + 4]);
        a[3] = fau(As[(r0 + 8) * 72 + kk + 4]);
        int kr0 = 128 + ks * 8 + tg;
#pragma unroll
        for (int nt = 0; nt < 8; nt++) {
            uint32_t b0 = fau(Gs[kr0 * 72 + nt * 8 + g]);
            uint32_t b1 = fau(Gs[(kr0 + 4) * 72 + nt * 8 + g]);
            mma_t32(c[nt], a, b0, b1);
        }
    }

    int l0 = lt * 128 + w * 16 + g;
#pragma unroll
    for (int nt = 0; nt < 8; nt++) {
        int col = nt * 8 + 2 * tg;
        float2 bb = *(const float2*)&bias[col];
        *(float2*)&out[((size_t)b * Ln + l0) * Cn + col] =
            make_float2(c[nt][0] + bb.x, c[nt][1] + bb.y);
        *(float2*)&out[((size_t)b * Ln + l0 + 8) * Cn + col] =
            make_float2(c[nt][2] + bb.x, c[nt][3] + bb.y);
    }
}

// ---------------------------------------------------------------------------
extern "C" void kernel_launch(void* const* d_in, const int* in_sizes, int n_in,
                              void* d_out, int out_size) {
    const float* x    = (const float*)d_in[0];
    const float* wr   = (const float*)d_in[1];
    const float* wi   = (const float*)d_in[2];
    const float* pw   = (const float*)d_in[3];
    const float* bias = (const float*)d_in[4];
    float* out = (float*)d_out;

    int smem3 = (192 * 72 + 128 * 72) * (int)sizeof(float);   // 92160 B
    cudaFuncSetAttribute(k_out, cudaFuncAttributeMaxDynamicSharedMemorySize, smem3);

    k_basis1<<<4096, 256>>>();
    k_basis3<<<4096, 256>>>();
    k_prepW<<<(Mn * Cn * Cn) / 256, 256>>>(wr, wi);
    k_dft<<<dim3(NCH, Bn), 256>>>(x);
    k_reduceP<<<(Bn * Jn * Cn) / 256, 256>>>();
    k_mix<<<dim3(Mn, Bn), Cn>>>();
    k_pwfill<<<Bn, 256>>>(pw);
    k_out<<<dim3(Ln / 128, Bn), 256, smem3>>>(x, bias, out);
}

// round 6
// speedup vs baseline: 3.7580x; 1.3155x over previous
#include <cuda_runtime.h>
#include <math.h>
#include <stdint.h>

#define Bn 32
#define Ln 8192
#define Cn 64
#define Mn 64
#define Jn 128          // 2*Mn (cos/sin rows)
#define JG 192          // Jn + Cn
#define NCH 32          // stage-1 K chunks (K=256 each)

// ---- scratch (device globals; no allocation allowed) ----
__device__ float g_b1frag[8 * 1024 * 32 * 4];   // stage-1 A frags [mt][ks][lane][q]  (4MB)
__device__ float g_b3frag[64 * 8 * 16 * 32 * 4];// stage-3 A frags [lt][mt][ks][lane][q] (4MB)
__device__ float g_Aw[Mn * Cn * Cn];            // [k][i][o] = alpha_k * Wr
__device__ float g_Bw[Mn * Cn * Cn];            // [k][i][o] = alpha_k * Wi
__device__ float g_Pp[NCH * Bn * Jn * Cn];      // stage-1 partials [ch][b][j][c] (33.5MB)
__device__ float g_G[Bn * JG * Cn];             // stage-3 B operand [b][j][o] (fp32)

// ---------------- helpers ----------------
__device__ __forceinline__ float totf32(float x) {
    uint32_t u;
    asm("cvt.rn.tf32.f32 %0, %1;" : "=r"(u) : "f"(x));
    return __uint_as_float(u);
}
__device__ __forceinline__ float4 totf32_4(float4 v) {
    v.x = totf32(v.x); v.y = totf32(v.y); v.z = totf32(v.z); v.w = totf32(v.w);
    return v;
}
__device__ __forceinline__ uint32_t fau(float x) { return __float_as_uint(x); }

// m16n8k8 tf32 mma: D(16x8 f32) += A(16x8 tf32, row) * B(8x8 tf32, col)
__device__ __forceinline__ void mma_t32(float c[4], const uint32_t a[4],
                                        uint32_t b0, uint32_t b1) {
    asm volatile(
        "mma.sync.aligned.m16n8k8.row.col.f32.tf32.tf32.f32 "
        "{%0,%1,%2,%3}, {%4,%5,%6,%7}, {%8,%9}, {%0,%1,%2,%3};"
        : "+f"(c[0]), "+f"(c[1]), "+f"(c[2]), "+f"(c[3])
        : "r"(a[0]), "r"(a[1]), "r"(a[2]), "r"(a[3]), "r"(b0), "r"(b1));
}

// ---------------------------------------------------------------------------
// Stage-1 A fragments: A[j][l], j = mt*16 + row, l = ks*8 + col.
// ---------------------------------------------------------------------------
__global__ void k_basis1() {
    int g = blockIdx.x * blockDim.x + threadIdx.x;   // 1M
    int q = g & 3, lane = (g >> 2) & 31, ks = (g >> 7) & 1023, mt = g >> 17;
    int j = mt * 16 + (lane >> 2) + (q & 1) * 8;
    int l = ks * 8 + (lane & 3) + ((q >> 1) & 1) * 4;
    int km = j >> 1;
    int m = (km * l) & (Ln - 1);                     // exact: < 2^19
    float th = (float)m * (6.2831853071795864769f / (float)Ln);
    float s, c; sincosf(th, &s, &c);
    g_b1frag[g] = totf32((j & 1) ? s : c);
}

// Stage-3 A fragments: A[l][j], l = lt*128 + mt*16 + row, j = ks*8 + col.
__global__ void k_basis3() {
    int g = blockIdx.x * blockDim.x + threadIdx.x;   // 1M
    int q = g & 3, lane = (g >> 2) & 31, ks = (g >> 7) & 15;
    int mt = (g >> 11) & 7, lt = g >> 14;
    int l = lt * 128 + mt * 16 + (lane >> 2) + (q & 1) * 8;
    int j = ks * 8 + (lane & 3) + ((q >> 1) & 1) * 4;
    int km = j >> 1;
    int m = (km * l) & (Ln - 1);
    float th = (float)m * (6.2831853071795864769f / (float)Ln);
    float s, c; sincosf(th, &s, &c);
    g_b3frag[g] = totf32((j & 1) ? s : c);
}

__global__ void k_prepW(const float* __restrict__ wr, const float* __restrict__ wi) {
    int g = blockIdx.x * blockDim.x + threadIdx.x;
    int o = g & 63, i = (g >> 6) & 63, k = g >> 12;
    float alpha = (k == 0 ? 1.0f : 2.0f) / (float)Ln;
    int widx = (i * Cn + o) * Mn + k;
    g_Aw[g] = alpha * wr[widx];
    g_Bw[g] = alpha * wi[widx];
}

// ---------------------------------------------------------------------------
// Stage 1: P[j=128][c=64] = sum_l basis[j,l]*x[l,c]; K=256 per block.
// 8 warps; warp w owns j-strip [w*16, w*16+16).  Double-buffered x staging,
// x loaded to regs (2 x float4) while MMAs run, STS after.
// ---------------------------------------------------------------------------
__global__ void __launch_bounds__(256) k_dft(const float* __restrict__ x) {
    int ch = blockIdx.x, b = blockIdx.y;
    __shared__ float Xs[2][32 * 72];                 // stride 72: conflict-free
    int t = threadIdx.x, w = t >> 5, lane = t & 31;
    int g = lane >> 2, tg = lane & 3;
    int row0 = t >> 4, c4 = t & 15;                  // staging coords (512 float4/tile)

    float c[8][4];
#pragma unroll
    for (int nt = 0; nt < 8; nt++)
#pragma unroll
        for (int q = 0; q < 4; q++) c[nt][q] = 0.0f;

    const float4* ap = (const float4*)g_b1frag + ((size_t)(w * 1024 + ch * 32) * 32 + lane);
    const float* xb = x + (size_t)b * Ln * Cn + (size_t)ch * 256 * Cn;

    // prologue: stage tile 0
    {
        float4 v0 = totf32_4(*(const float4*)&xb[row0 * Cn + c4 * 4]);
        float4 v1 = totf32_4(*(const float4*)&xb[(row0 + 16) * Cn + c4 * 4]);
        *(float4*)&Xs[0][row0 * 72 + c4 * 4] = v0;
        *(float4*)&Xs[0][(row0 + 16) * 72 + c4 * 4] = v1;
    }
    __syncthreads();

    for (int kc = 0; kc < 8; kc++) {
        int cur = kc & 1;
        float4 n0, n1;
        if (kc < 7) {                                // issue next-tile LDG early
            const float* xn = xb + (kc + 1) * 32 * Cn;
            n0 = *(const float4*)&xn[row0 * Cn + c4 * 4];
            n1 = *(const float4*)&xn[(row0 + 16) * Cn + c4 * 4];
        }
        float4 af[4];                                // prefetch A frags
#pragma unroll
        for (int s = 0; s < 4; s++) af[s] = ap[(kc * 4 + s) * 32];
#pragma unroll
        for (int ks4 = 0; ks4 < 4; ks4++) {
            uint32_t a[4] = { fau(af[ks4].x), fau(af[ks4].y),
                              fau(af[ks4].z), fau(af[ks4].w) };
            int kr0 = ks4 * 8 + tg;
#pragma unroll
            for (int nt = 0; nt < 8; nt++) {
                uint32_t b0 = fau(Xs[cur][kr0 * 72 + nt * 8 + g]);
                uint32_t b1 = fau(Xs[cur][(kr0 + 4) * 72 + nt * 8 + g]);
                mma_t32(c[nt], a, b0, b1);
            }
        }
        if (kc < 7) {
            *(float4*)&Xs[cur ^ 1][row0 * 72 + c4 * 4] = totf32_4(n0);
            *(float4*)&Xs[cur ^ 1][(row0 + 16) * 72 + c4 * 4] = totf32_4(n1);
        }
        __syncthreads();
    }

    float* dst = g_Pp + ((size_t)(ch * Bn + b) * Jn) * Cn;
    int j0 = w * 16 + g;
#pragma unroll
    for (int nt = 0; nt < 8; nt++) {
        *(float2*)&dst[j0 * Cn + nt * 8 + 2 * tg]       = make_float2(c[nt][0], c[nt][1]);
        *(float2*)&dst[(j0 + 8) * Cn + nt * 8 + 2 * tg] = make_float2(c[nt][2], c[nt][3]);
    }
}

// ---------------------------------------------------------------------------
// Stage 2: fused partial-reduce + complex mix.  P0=XFr, P1=-XFi.
// ---------------------------------------------------------------------------
__global__ void k_mix() {
    int k = blockIdx.x, b = blockIdx.y, o = threadIdx.x;
    __shared__ float P0[Cn], P1[Cn];
    float p0 = 0.0f, p1 = 0.0f;
#pragma unroll 4
    for (int ch = 0; ch < NCH; ch++) {
        const float* src = g_Pp + ((size_t)(ch * Bn + b) * Jn + 2 * k) * Cn;
        p0 += src[o];
        p1 += src[Cn + o];
    }
    P0[o] = p0; P1[o] = p1;
    __syncthreads();
    float gr = 0.0f, gi = 0.0f;
#pragma unroll 8
    for (int i = 0; i < Cn; i++) {
        float a  = g_Aw[(k * Cn + i) * Cn + o];
        float bb = g_Bw[(k * Cn + i) * Cn + o];
        float pr = P0[i], pi = P1[i];
        gr += pr * a + pi * bb;
        gi += pi * a - pr * bb;
    }
    g_G[(b * JG + 2 * k) * Cn + o]     = gr;
    g_G[(b * JG + 2 * k + 1) * Cn + o] = gi;
}

__global__ void k_pwfill(const float* __restrict__ pw) {
    int b = blockIdx.x, t = threadIdx.x;
#pragma unroll
    for (int i = 0; i < 16; i++) {
        int idx = t + i * 256;
        int o = idx & 63, ic = idx >> 6;
        g_G[(b * JG + Jn + ic) * Cn + o] = pw[o * Cn + ic];
    }
}

// ---------------------------------------------------------------------------
// Stage 3: out[l=128][o=64] = sum_{j<192} bigA[l,j]*G[j,o] + bias.
// ksteps 0..15: basis frags from global; 16..23: x rows from smem As.
// ---------------------------------------------------------------------------
__global__ void __launch_bounds__(256) k_out(const float* __restrict__ x,
                                             const float* __restrict__ bias,
                                             float* __restrict__ out) {
    int lt = blockIdx.x, b = blockIdx.y;
    extern __shared__ __align__(16) float sm[];
    float* Gs = sm;                                  // [192][72]
    float* As = sm + 192 * 72;                       // [128][72]
    int t = threadIdx.x, w = t >> 5, lane = t & 31;
    int g = lane >> 2, tg = lane & 3;

    {                                                // stage G: 3072 float4
        const float4* src = (const float4*)(g_G + (size_t)b * JG * Cn);
#pragma unroll
        for (int i = 0; i < 12; i++) {
            int idx = t + i * 256;                   // [j][c4]
            int j = idx >> 4, cc = idx & 15;
            *(float4*)&Gs[j * 72 + cc * 4] = totf32_4(src[idx]);
        }
        const float4* xs = (const float4*)(x + ((size_t)b * Ln + lt * 128) * Cn);
#pragma unroll
        for (int i = 0; i < 8; i++) {                // stage x: 2048 float4
            int idx = t + i * 256;
            int r = idx >> 4, cc = idx & 15;
            *(float4*)&As[r * 72 + cc * 4] = totf32_4(xs[idx]);
        }
    }
    __syncthreads();

    float c[8][4];
#pragma unroll
    for (int nt = 0; nt < 8; nt++)
#pragma unroll
        for (int q = 0; q < 4; q++) c[nt][q] = 0.0f;

    const float4* ap = (const float4*)g_b3frag + ((size_t)((lt * 8 + w) * 16) * 32 + lane);
#pragma unroll
    for (int ks = 0; ks < 16; ks++) {                // basis part (K 0..127)
        float4 af = ap[ks * 32];
        uint32_t a[4] = { fau(af.x), fau(af.y), fau(af.z), fau(af.w) };
        int kr0 = ks * 8 + tg;
#pragma unroll
        for (int nt = 0; nt < 8; nt++) {
            uint32_t b0 = fau(Gs[kr0 * 72 + nt * 8 + g]);
            uint32_t b1 = fau(Gs[(kr0 + 4) * 72 + nt * 8 + g]);
            mma_t32(c[nt], a, b0, b1);
        }
    }
#pragma unroll
    for (int ks = 0; ks < 8; ks++) {                 // x part (K 128..191)
        int kk = ks * 8 + tg;
        int r0 = w * 16 + g;
        uint32_t a[4];
        a[0] = fau(As[r0 * 72 + kk]);
        a[1] = fau(As[(r0 + 8) * 72 + kk]);
        a[2] = fau(As[r0 * 72 + kk + 4]);
        a[3] = fau(As[(r0 + 8) * 72 + kk + 4]);
        int kr0 = 128 + ks * 8 + tg;
#pragma unroll
        for (int nt = 0; nt < 8; nt++) {
            uint32_t b0 = fau(Gs[kr0 * 72 + nt * 8 + g]);
            uint32_t b1 = fau(Gs[(kr0 + 4) * 72 + nt * 8 + g]);
            mma_t32(c[nt], a, b0, b1);
        }
    }

    int l0 = lt * 128 + w * 16 + g;
#pragma unroll
    for (int nt = 0; nt < 8; nt++) {
        int col = nt * 8 + 2 * tg;
        float2 bb = *(const float2*)&bias[col];
        *(float2*)&out[((size_t)b * Ln + l0) * Cn + col] =
            make_float2(c[nt][0] + bb.x, c[nt][1] + bb.y);
        *(float2*)&out[((size_t)b * Ln + l0 + 8) * Cn + col] =
            make_float2(c[nt][2] + bb.x, c[nt][3] + bb.y);
    }
}

// ---------------------------------------------------------------------------
extern "C" void kernel_launch(void* const* d_in, const int* in_sizes, int n_in,
                              void* d_out, int out_size) {
    const float* x    = (const float*)d_in[0];
    const float* wr   = (const float*)d_in[1];
    const float* wi   = (const float*)d_in[2];
    const float* pw   = (const float*)d_in[3];
    const float* bias = (const float*)d_in[4];
    float* out = (float*)d_out;

    int smem3 = (192 * 72 + 128 * 72) * (int)sizeof(float);   // 92160 B
    cudaFuncSetAttribute(k_out, cudaFuncAttributeMaxDynamicSharedMemorySize, smem3);

    k_basis1<<<4096, 256>>>();
    k_basis3<<<4096, 256>>>();
    k_prepW<<<(Mn * Cn * Cn) / 256, 256>>>(wr, wi);
    k_dft<<<dim3(NCH, Bn), 256>>>(x);
    k_mix<<<dim3(Mn, Bn), Cn>>>();
    k_pwfill<<<Bn, 256>>>(pw);
    k_out<<<dim3(Ln / 128, Bn), 256, smem3>>>(x, bias, out);
}